// round 1
// baseline (speedup 1.0000x reference)
#include <cuda_runtime.h>
#include <math.h>

// Problem dims (fixed by the dataset)
#define M_DIM 16384   // 32*512
#define K_DIM 768
#define N_DIM 3072

// Scratch for normalized x (no cudaMalloc allowed)
__device__ float g_xn[M_DIM * K_DIM];

// ---------------------------------------------------------------------------
// Kernel 1: LayerNorm over last dim (768), eps = 1e-12, affine.
// One block per row, 256 threads, each thread handles 3 elements.
// ---------------------------------------------------------------------------
__global__ __launch_bounds__(256) void ln_kernel(
    const float* __restrict__ x,
    const float* __restrict__ gamma,
    const float* __restrict__ beta)
{
    const int row = blockIdx.x;
    const int tid = threadIdx.x;
    const float* xr = x + (size_t)row * K_DIM;
    float* outr = g_xn + (size_t)row * K_DIM;

    float v0 = xr[tid];
    float v1 = xr[tid + 256];
    float v2 = xr[tid + 512];

    float s  = v0 + v1 + v2;
    float s2 = v0 * v0 + v1 * v1 + v2 * v2;

    // block reduce (sum, sumsq)
    __shared__ float red[2][32];
    // warp reduce
    #pragma unroll
    for (int off = 16; off > 0; off >>= 1) {
        s  += __shfl_xor_sync(0xffffffffu, s,  off);
        s2 += __shfl_xor_sync(0xffffffffu, s2, off);
    }
    const int wid = tid >> 5;
    const int lid = tid & 31;
    if (lid == 0) { red[0][wid] = s; red[1][wid] = s2; }
    __syncthreads();
    if (wid == 0) {
        s  = (lid < 8) ? red[0][lid] : 0.0f;
        s2 = (lid < 8) ? red[1][lid] : 0.0f;
        #pragma unroll
        for (int off = 4; off > 0; off >>= 1) {
            s  += __shfl_xor_sync(0xffffffffu, s,  off);
            s2 += __shfl_xor_sync(0xffffffffu, s2, off);
        }
        if (lid == 0) { red[0][0] = s; red[1][0] = s2; }
    }
    __syncthreads();
    const float inv_n = 1.0f / (float)K_DIM;
    const float mu  = red[0][0] * inv_n;
    const float var = fmaxf(red[1][0] * inv_n - mu * mu, 0.0f);
    const float rstd = rsqrtf(var + 1e-12f);

    outr[tid]       = (v0 - mu) * rstd * gamma[tid]       + beta[tid];
    outr[tid + 256] = (v1 - mu) * rstd * gamma[tid + 256] + beta[tid + 256];
    outr[tid + 512] = (v2 - mu) * rstd * gamma[tid + 512] + beta[tid + 512];
}

// ---------------------------------------------------------------------------
// Kernel 2: C = GELU( xn(16384x768) @ W(768x3072) + b ), exact erf GELU.
// 128x128 block tile, BK=16, 256 threads, 8x8 microtile per thread.
// ---------------------------------------------------------------------------
#define BM 128
#define BN 128
#define BK 16

__global__ __launch_bounds__(256) void gemm_gelu_kernel(
    const float* __restrict__ A,   // g_xn, [M, K] row-major
    const float* __restrict__ W,   // [K, N] row-major
    const float* __restrict__ b,   // [N]
    float* __restrict__ C)         // [M, N]
{
    __shared__ float As[BK][BM];       // transposed A tile
    __shared__ float Bs[BK][BN];

    const int tid = threadIdx.x;              // 0..255
    const int tx = tid & 15;                  // 0..15 -> N microtiles
    const int ty = tid >> 4;                  // 0..15 -> M microtiles
    const int bm = blockIdx.y * BM;
    const int bn = blockIdx.x * BN;

    float acc[8][8];
    #pragma unroll
    for (int i = 0; i < 8; i++)
        #pragma unroll
        for (int j = 0; j < 8; j++) acc[i][j] = 0.0f;

    // global load indices
    // A tile: 128 rows x 16 cols = 512 float4, 2 per thread
    const int a_row0 = (tid * 2) / 4;           // 4 float4 per row
    const int a_col0 = ((tid * 2) % 4) * 4;     // starting float col of float4
    // B tile: 16 rows x 128 cols = 512 float4, 2 per thread
    const int b_row0 = (tid * 2) / 32;          // 32 float4 per row
    const int b_col0 = ((tid * 2) % 32) * 4;

    for (int k0 = 0; k0 < K_DIM; k0 += BK) {
        // load A (transpose into As[k][m])
        #pragma unroll
        for (int i = 0; i < 2; i++) {
            const int idx = tid * 2 + i;
            const int row = idx >> 2;
            const int col = (idx & 3) * 4;
            float4 v = *(const float4*)&A[(size_t)(bm + row) * K_DIM + k0 + col];
            As[col + 0][row] = v.x;
            As[col + 1][row] = v.y;
            As[col + 2][row] = v.z;
            As[col + 3][row] = v.w;
        }
        // load B
        #pragma unroll
        for (int i = 0; i < 2; i++) {
            const int idx = tid * 2 + i;
            const int row = idx >> 5;
            const int col = (idx & 31) * 4;
            *(float4*)&Bs[row][col] =
                *(const float4*)&W[(size_t)(k0 + row) * N_DIM + bn + col];
        }
        __syncthreads();

        #pragma unroll
        for (int kk = 0; kk < BK; kk++) {
            float4 a0 = *(const float4*)&As[kk][ty * 8];
            float4 a1 = *(const float4*)&As[kk][ty * 8 + 4];
            float4 b0 = *(const float4*)&Bs[kk][tx * 8];
            float4 b1 = *(const float4*)&Bs[kk][tx * 8 + 4];
            float ar[8] = {a0.x, a0.y, a0.z, a0.w, a1.x, a1.y, a1.z, a1.w};
            float br[8] = {b0.x, b0.y, b0.z, b0.w, b1.x, b1.y, b1.z, b1.w};
            #pragma unroll
            for (int i = 0; i < 8; i++)
                #pragma unroll
                for (int j = 0; j < 8; j++)
                    acc[i][j] = fmaf(ar[i], br[j], acc[i][j]);
        }
        __syncthreads();
    }

    // epilogue: bias + exact GELU, vectorized store
    #pragma unroll
    for (int i = 0; i < 8; i++) {
        const int row = bm + ty * 8 + i;
        float* crow = C + (size_t)row * N_DIM + bn + tx * 8;
        #pragma unroll
        for (int j4 = 0; j4 < 2; j4++) {
            float4 out;
            #pragma unroll
            for (int j = 0; j < 4; j++) {
                const int col = bn + tx * 8 + j4 * 4 + j;
                float h = acc[i][j4 * 4 + j] + b[col];
                float g = 0.5f * h * (1.0f + erff(h * 0.70710678118654752f));
                ((float*)&out)[j] = g;
            }
            *(float4*)(crow + j4 * 4) = out;
        }
    }
}

// ---------------------------------------------------------------------------
extern "C" void kernel_launch(void* const* d_in, const int* in_sizes, int n_in,
                              void* d_out, int out_size)
{
    const float* x     = (const float*)d_in[0];
    const float* gamma = (const float*)d_in[1];
    const float* beta  = (const float*)d_in[2];
    const float* W     = (const float*)d_in[3];
    const float* b     = (const float*)d_in[4];
    float* out = (float*)d_out;

    float* xn;
    cudaGetSymbolAddress((void**)&xn, g_xn);

    ln_kernel<<<M_DIM, 256>>>(x, gamma, beta);
    dim3 grid(N_DIM / BN, M_DIM / BM);
    gemm_gelu_kernel<<<grid, 256>>>(xn, W, b, out);
}

// round 3
// speedup vs baseline: 1.9594x; 1.9594x over previous
#include <cuda_runtime.h>
#include <cstdint>
#include <math.h>

#define M_DIM 16384
#define K_DIM 768
#define N_DIM 3072

// ---------------- scratch (no cudaMalloc allowed) ----------------
__device__ uint16_t g_Ahi[M_DIM * K_DIM];   // bf16 bits
__device__ uint16_t g_Alo[M_DIM * K_DIM];
__device__ uint16_t g_Bhi[N_DIM * K_DIM];   // W transposed [N, K], bf16
__device__ uint16_t g_Blo[N_DIM * K_DIM];

// ---------------- helpers ----------------
__device__ __forceinline__ uint32_t smem_u32(const void* p) {
    uint32_t a;
    asm("{ .reg .u64 t; cvta.to.shared.u64 t, %1; cvt.u32.u64 %0, t; }" : "=r"(a) : "l"(p));
    return a;
}
__device__ __forceinline__ uint16_t bf16_hi(float x) {
    uint16_t h;
    asm("cvt.rn.bf16.f32 %0, %1;" : "=h"(h) : "f"(x));
    return h;
}
__device__ __forceinline__ float bf16_to_f(uint16_t h) {
    uint32_t u = (uint32_t)h << 16;
    return __uint_as_float(u);
}
__device__ __forceinline__ void cp_async16(uint32_t dst, const void* src) {
    asm volatile("cp.async.cg.shared.global [%0], [%1], 16;"
                 :: "r"(dst), "l"(__cvta_generic_to_global(src)) : "memory");
}
#define CP_COMMIT() asm volatile("cp.async.commit_group;" ::: "memory")
#define CP_WAIT(n)  asm volatile("cp.async.wait_group %0;" :: "n"(n) : "memory")

__device__ __forceinline__ void ldmatrix_x4(uint32_t* r, uint32_t addr) {
    asm volatile("ldmatrix.sync.aligned.m8n8.x4.shared.b16 {%0,%1,%2,%3}, [%4];"
                 : "=r"(r[0]), "=r"(r[1]), "=r"(r[2]), "=r"(r[3]) : "r"(addr));
}
__device__ __forceinline__ void mma_bf16(float* d, const uint32_t* a,
                                         uint32_t b0, uint32_t b1) {
    asm volatile(
        "mma.sync.aligned.m16n8k16.row.col.f32.bf16.bf16.f32 "
        "{%0,%1,%2,%3}, {%4,%5,%6,%7}, {%8,%9}, {%0,%1,%2,%3};"
        : "+f"(d[0]), "+f"(d[1]), "+f"(d[2]), "+f"(d[3])
        : "r"(a[0]), "r"(a[1]), "r"(a[2]), "r"(a[3]), "r"(b0), "r"(b1));
}

// ---------------------------------------------------------------------------
// Kernel 1: LayerNorm + bf16 hi/lo split
// ---------------------------------------------------------------------------
__global__ __launch_bounds__(256) void ln_split_kernel(
    const float* __restrict__ x,
    const float* __restrict__ gamma,
    const float* __restrict__ beta)
{
    const int row = blockIdx.x;
    const int tid = threadIdx.x;
    const float* xr = x + (size_t)row * K_DIM;

    float v0 = xr[tid];
    float v1 = xr[tid + 256];
    float v2 = xr[tid + 512];

    float s  = v0 + v1 + v2;
    float s2 = v0 * v0 + v1 * v1 + v2 * v2;

    __shared__ float red[2][32];
    #pragma unroll
    for (int off = 16; off > 0; off >>= 1) {
        s  += __shfl_xor_sync(0xffffffffu, s,  off);
        s2 += __shfl_xor_sync(0xffffffffu, s2, off);
    }
    const int wid = tid >> 5, lid = tid & 31;
    if (lid == 0) { red[0][wid] = s; red[1][wid] = s2; }
    __syncthreads();
    if (wid == 0) {
        s  = (lid < 8) ? red[0][lid] : 0.0f;
        s2 = (lid < 8) ? red[1][lid] : 0.0f;
        #pragma unroll
        for (int off = 4; off > 0; off >>= 1) {
            s  += __shfl_xor_sync(0xffffffffu, s,  off);
            s2 += __shfl_xor_sync(0xffffffffu, s2, off);
        }
        if (lid == 0) { red[0][0] = s; red[1][0] = s2; }
    }
    __syncthreads();
    const float inv_n = 1.0f / (float)K_DIM;
    const float mu  = red[0][0] * inv_n;
    const float var = fmaxf(red[1][0] * inv_n - mu * mu, 0.0f);
    const float rstd = rsqrtf(var + 1e-12f);

    #pragma unroll
    for (int i = 0; i < 3; i++) {
        const int c = tid + i * 256;
        float v = (i == 0) ? v0 : (i == 1 ? v1 : v2);
        float xn = (v - mu) * rstd * gamma[c] + beta[c];
        uint16_t hi = bf16_hi(xn);
        uint16_t lo = bf16_hi(xn - bf16_to_f(hi));
        const size_t idx = (size_t)row * K_DIM + c;
        g_Ahi[idx] = hi;
        g_Alo[idx] = lo;
    }
}

// ---------------------------------------------------------------------------
// Kernel 2: transpose W [K,N] -> [N,K] with bf16 hi/lo split
// ---------------------------------------------------------------------------
__global__ __launch_bounds__(256) void wsplit_kernel(const float* __restrict__ W)
{
    __shared__ float tile[32][33];
    const int tx = threadIdx.x, ty = threadIdx.y;   // block (32, 8)
    const int n0 = blockIdx.x * 32, k0 = blockIdx.y * 32;

    #pragma unroll
    for (int j = 0; j < 4; j++)
        tile[ty + 8 * j][tx] = W[(size_t)(k0 + ty + 8 * j) * N_DIM + n0 + tx];
    __syncthreads();
    #pragma unroll
    for (int j = 0; j < 4; j++) {
        float v = tile[tx][ty + 8 * j];
        uint16_t hi = bf16_hi(v);
        uint16_t lo = bf16_hi(v - bf16_to_f(hi));
        const size_t idx = (size_t)(n0 + ty + 8 * j) * K_DIM + k0 + tx;
        g_Bhi[idx] = hi;
        g_Blo[idx] = lo;
    }
}

// ---------------------------------------------------------------------------
// Kernel 3: bf16x3 mma.sync GEMM + bias + exact erf GELU
// CTA tile 128x128, BK=32, 2-stage cp.async, 8 warps (warp tile 32x64).
// Virtual K = 3 * 768 over segments (Ahi,Bhi), (Ahi,Blo), (Alo,Bhi).
// ---------------------------------------------------------------------------
#define BM 128
#define BN 128
#define BK 32
#define ROWH 40          // halves per smem row (32 data + 8 pad) = 80 bytes
#define KSTEPS 24        // 768 / 32
#define NSTEP  72        // 3 * 24

__global__ __launch_bounds__(256, 2) void gemm_bf16x3_kernel(
    const float* __restrict__ bias, float* __restrict__ C)
{
    __shared__ uint16_t As[2][BM * ROWH];
    __shared__ uint16_t Bs[2][BN * ROWH];

    const int tid = threadIdx.x;
    const int wid = tid >> 5, lane = tid & 31;
    const int bn = blockIdx.x * BN;
    const int bm = blockIdx.y * BM;
    const int wm = (wid >> 1) * 32;   // 4 warps along M
    const int wn = (wid & 1) * 64;    // 2 warps along N

    float acc[2][8][4];
    #pragma unroll
    for (int mt = 0; mt < 2; mt++)
        #pragma unroll
        for (int nt = 0; nt < 8; nt++)
            #pragma unroll
            for (int q = 0; q < 4; q++) acc[mt][nt][q] = 0.0f;

    const uint32_t sA0 = smem_u32(&As[0][0]);
    const uint32_t sB0 = smem_u32(&Bs[0][0]);
    const uint32_t stageA = (uint32_t)(BM * ROWH * 2);
    const uint32_t stageB = (uint32_t)(BN * ROWH * 2);

    // per-thread load geometry: 512 16B chunks per operand tile, 2 per thread
    const int lr = tid >> 1;          // 0..127 (reused below via idx math)

    auto load_stage = [&](int st, int step) {
        const int seg = step / KSTEPS;
        const int k0 = (step % KSTEPS) * BK;
        const uint16_t* Asrc = (seg < 2 ? g_Ahi : g_Alo);
        const uint16_t* Bsrc = (seg == 1 ? g_Blo : g_Bhi);
        #pragma unroll
        for (int i = 0; i < 2; i++) {
            const int idx = tid + i * 256;       // 0..511
            const int r = idx >> 2, c = idx & 3; // row, 16B chunk
            const uint32_t soff = (uint32_t)(r * ROWH + c * 8) * 2;
            cp_async16(sA0 + st * stageA + soff,
                       Asrc + (size_t)(bm + r) * K_DIM + k0 + c * 8);
            cp_async16(sB0 + st * stageB + soff,
                       Bsrc + (size_t)(bn + r) * K_DIM + k0 + c * 8);
        }
        CP_COMMIT();
    };

    load_stage(0, 0);

    for (int step = 0; step < NSTEP; step++) {
        const int st = step & 1;
        if (step + 1 < NSTEP) {
            load_stage(st ^ 1, step + 1);
            CP_WAIT(1);
        } else {
            CP_WAIT(0);
        }
        __syncthreads();

        #pragma unroll
        for (int kk = 0; kk < 2; kk++) {        // two k16 steps per BK=32
            const int chunk = kk * 2 + (lane >> 4);   // 16B chunk col for ldmatrix
            uint32_t a[2][4];
            #pragma unroll
            for (int mt = 0; mt < 2; mt++) {
                const int row = wm + mt * 16 + (lane & 15);
                ldmatrix_x4(a[mt], sA0 + st * stageA
                                   + (uint32_t)(row * ROWH) * 2 + chunk * 16);
            }
            uint32_t b[4][4];
            #pragma unroll
            for (int g = 0; g < 4; g++) {
                const int row = wn + g * 16 + (lane & 15);
                ldmatrix_x4(b[g], sB0 + st * stageB
                                  + (uint32_t)(row * ROWH) * 2 + chunk * 16);
            }
            #pragma unroll
            for (int mt = 0; mt < 2; mt++)
                #pragma unroll
                for (int nt = 0; nt < 8; nt++)
                    mma_bf16(acc[mt][nt], a[mt],
                             b[nt >> 1][nt & 1], b[nt >> 1][2 + (nt & 1)]);
        }
        __syncthreads();
    }

    // epilogue: bias + exact erf GELU
    const int r0 = bm + wm + (lane >> 2);
    const int c0 = bn + wn + (lane & 3) * 2;
    #pragma unroll
    for (int mt = 0; mt < 2; mt++) {
        #pragma unroll
        for (int nt = 0; nt < 8; nt++) {
            const int col = c0 + nt * 8;
            const float b0 = bias[col], b1 = bias[col + 1];
            #pragma unroll
            for (int half = 0; half < 2; half++) {
                const int row = r0 + mt * 16 + half * 8;
                float h0 = acc[mt][nt][half * 2 + 0] + b0;
                float h1 = acc[mt][nt][half * 2 + 1] + b1;
                float2 o;
                o.x = 0.5f * h0 * (1.0f + erff(h0 * 0.70710678118654752f));
                o.y = 0.5f * h1 * (1.0f + erff(h1 * 0.70710678118654752f));
                *(float2*)&C[(size_t)row * N_DIM + col] = o;
            }
        }
    }
    (void)lr;
}

// ---------------------------------------------------------------------------
extern "C" void kernel_launch(void* const* d_in, const int* in_sizes, int n_in,
                              void* d_out, int out_size)
{
    const float* x     = (const float*)d_in[0];
    const float* gamma = (const float*)d_in[1];
    const float* beta  = (const float*)d_in[2];
    const float* W     = (const float*)d_in[3];
    const float* b     = (const float*)d_in[4];
    float* out = (float*)d_out;

    ln_split_kernel<<<M_DIM, 256>>>(x, gamma, beta);
    wsplit_kernel<<<dim3(N_DIM / 32, K_DIM / 32), dim3(32, 8)>>>(W);
    gemm_bf16x3_kernel<<<dim3(N_DIM / BN, M_DIM / BM), 256>>>(b, out);
}